// round 14
// baseline (speedup 1.0000x reference)
#include <cuda_runtime.h>
#include <cuda_bf16.h>
#include <cuda_fp16.h>
#include <cuda_fp8.h>
#include <math.h>

typedef unsigned int uint;
typedef unsigned short ushort;

#define S 128
#define T 128
#define NB 16
#define NH 64
#define DH 128
#define TS 15
#define NS 16
#define NTILE 9
#define TPB 512
#define TOUT 107
#define NSTEP 127

#define WSCALE 64.0f
#define WISCALE 0.015625f

// Warp-major fp8(e4m3) weights (scaled x64), gate-interleaved N, k32 fragments.
// fBd4[((kt*16 + w)*2 + half)*32 + lane]: half0={j0b0,j0b1,j1b0,j1b1}, half1={j2..j3}
__device__ uint4 fBn4[6*8*2*32];
__device__ uint4 fBs4[6*8*2*32];
__device__ uint4 fBd4[16*16*2*32];

// Boundary publish ring: [buf][b][tile][slot][256]
// slot0 = site s0, slot1 = site s0+13; [0:64) hn, [64:128) hs, [128:256) hd
__device__ float g_pub[2][NB][NTILE][2][256];
__device__ int g_flag[NB*NTILE];

// ---- smem offsets (floats) ----
#define OFF_XIN 0                      // 64
#define OFF_O0  (OFF_XIN + 64)         // 16
#define OFF_O1  (OFF_O0 + 16)          // 16
#define OFF_HDC (OFF_O1 + 16)          // 2048
#define OFF_NSF (OFF_HDC + 2048)       // 1536 uints: An@0 (768), As@768
#define OFF_ADF (OFF_NSF + 1536)       // 2048 uints
#define SMEM_FLOATS (OFF_ADF + 2048)

#define MMA8(c, a0,a1,a2,a3, b0,b1) \
  asm volatile("mma.sync.aligned.m16n8k32.row.col.f32.e4m3.e4m3.f32 " \
    "{%0,%1,%2,%3}, {%4,%5,%6,%7}, {%8,%9}, {%0,%1,%2,%3};" \
    : "+f"(c[0]), "+f"(c[1]), "+f"(c[2]), "+f"(c[3]) \
    : "r"(a0), "r"(a1), "r"(a2), "r"(a3), "r"(b0), "r"(b1))

__device__ __forceinline__ float tanhap(float x) {
    float y;
    asm("tanh.approx.f32 %0, %1;" : "=f"(y) : "f"(x));
    return y;
}
__device__ __forceinline__ float sigm(float x) {
    return fmaf(tanhap(0.5f*x), 0.5f, 0.5f);
}

// pack 2 floats -> 2 e4m3 bytes; low byte = lo (lower k)
__device__ __forceinline__ ushort packe2(float lo, float hi) {
    ushort r;
    asm("cvt.rn.satfinite.e4m3x2.f32 %0, %1, %2;" : "=h"(r) : "f"(hi), "f"(lo));
    return r;
}

// fp8 fragment addressing: element (row r, col k) in k32 fragment array
// reg = (r>>3) + ((ec>>4)<<1); lane = (r&7)*4 + ((ec&15)>>2); byte = ec&3
__device__ __forceinline__ int frag8_off(int r, int k) {
    int kt = k >> 5, ec = k & 31;
    int reg = (r >> 3) + ((ec >> 4) << 1);
    int ln  = ((r & 7) << 2) + ((ec & 15) >> 2);
    return ((kt*32 + ln)*4 + reg)*4 + (ec & 3);
}
__device__ __forceinline__ void store_fragp8(uint* base, int r, int k, ushort v) {
    *(ushort*)((char*)base + frag8_off(r, k)) = v;
}
__device__ __forceinline__ void store_frag8(uint* base, int r, int k, float val) {
    __nv_fp8_e4m3 q(val);
    ((char*)base)[frag8_off(r, k)] = (char)q.__x;
}

__device__ __forceinline__ uint pack8w(float v0, float v1, float v2, float v3) {
    __nv_fp8_e4m3 a(v0 * WSCALE), b(v1 * WSCALE), c(v2 * WSCALE), d(v3 * WSCALE);
    return (uint)a.__x | ((uint)b.__x << 8) | ((uint)c.__x << 16) | ((uint)d.__x << 24);
}

__global__ void init_flags_kernel() {
    int i = blockIdx.x * blockDim.x + threadIdx.x;
    if (i < NB*NTILE) g_flag[i] = 0;
}

__global__ void repack_kernel(
    const float* __restrict__ nWh, const float* __restrict__ nWa, const float* __restrict__ nWb,
    const float* __restrict__ sWh, const float* __restrict__ sWa, const float* __restrict__ sWb,
    const float* __restrict__ dWx, const float* __restrict__ dWh,
    const float* __restrict__ dWa, const float* __restrict__ dWb)
{
    int idx = blockIdx.x * blockDim.x + threadIdx.x;
    if (idx < 16*16*2*32) {
        int lane = idx & 31, half = (idx >> 5) & 1, wq = (idx >> 6) & 15, kt = idx >> 10;
        uint wd[4];
        #pragma unroll
        for (int jj = 0; jj < 2; jj++) {
            int jg = wq*4 + half*2 + jj;
            int nprime = jg*8 + (lane >> 2);
            int e = ((nprime >> 5) << 3) | (nprime & 7);
            int g = (nprime >> 3) & 3;
            int n = g*128 + e;
            #pragma unroll
            for (int bsel = 0; bsel < 2; bsel++) {
                float v[4];
                #pragma unroll
                for (int byt = 0; byt < 4; byt++) {
                    int kk = kt*32 + (lane & 3)*4 + bsel*16 + byt;
                    float x;
                    if      (kk < 128) x = dWx[kk*512 + n];
                    else if (kk < 256) x = dWh[(kk-128)*512 + n];
                    else if (kk < 384) x = dWa[(kk-256)*512 + n];
                    else               x = dWb[(kk-384)*512 + n];
                    v[byt] = x;
                }
                wd[jj*2 + bsel] = pack8w(v[0], v[1], v[2], v[3]);
            }
        }
        fBd4[idx] = make_uint4(wd[0], wd[1], wd[2], wd[3]);
    }
    int idx2 = idx - 16*16*2*32;
    if (idx2 >= 0 && idx2 < 2*6*8*2*32) {
        int set = idx2 / 3072;
        int e_ = idx2 % 3072;
        int lane = e_ & 31, half = (e_ >> 5) & 1, gq = (e_ >> 6) & 7, kt = e_ >> 9;
        const float* Wh = set ? sWh : nWh;
        const float* Wa = set ? sWa : nWa;
        const float* Wb = set ? sWb : nWb;
        uint wd[4];
        #pragma unroll
        for (int jj = 0; jj < 2; jj++) {
            int jg = gq*4 + half*2 + jj;
            int nprime = jg*8 + (lane >> 2);
            int e = ((nprime >> 5) << 3) | (nprime & 7);
            int g = (nprime >> 3) & 3;
            int n = g*64 + e;
            #pragma unroll
            for (int bsel = 0; bsel < 2; bsel++) {
                float v[4];
                #pragma unroll
                for (int byt = 0; byt < 4; byt++) {
                    int kk = kt*32 + (lane & 3)*4 + bsel*16 + byt;
                    float x;
                    if      (kk < 64)  x = Wh[kk*256 + n];
                    else if (kk < 128) x = Wa[(kk-64)*256 + n];
                    else               x = Wb[(kk-128)*256 + n];
                    v[byt] = x;
                }
                wd[jj*2 + bsel] = pack8w(v[0], v[1], v[2], v[3]);
            }
        }
        (set ? fBs4 : fBn4)[e_] = make_uint4(wd[0], wd[1], wd[2], wd[3]);
    }
}

__global__ void __launch_bounds__(TPB, 1) persistent_kernel(
    const float* __restrict__ xg,
    const float* __restrict__ nWx, const float* __restrict__ nb,
    const float* __restrict__ sWx, const float* __restrict__ sb,
    const float* __restrict__ db,
    const float* __restrict__ onW, const float* __restrict__ onb,
    const float* __restrict__ osW, const float* __restrict__ osb,
    float* __restrict__ out)
{
    extern __shared__ float sm[];
    float* xin = sm + OFF_XIN;   // [16][4]
    float* o0s = sm + OFF_O0;
    float* o1s = sm + OFF_O1;
    float* hdc = sm + OFF_HDC;   // [16*128]
    uint*  nsU = (uint*)(sm + OFF_NSF);   // An@0 (768), As@768
    uint4* nsF4 = (uint4*)(sm + OFF_NSF); // An: 192 uint4, As: +192
    uint*  adU = (uint*)(sm + OFF_ADF);   // 2048
    uint4* AdF4 = (uint4*)(sm + OFF_ADF); // 512 uint4

    const int tid  = threadIdx.x;
    const int w    = tid >> 5;
    const int lane = tid & 31;
    const int tile = blockIdx.x;
    const int bb   = blockIdx.y;
    const int s0   = tile * TS;

    const int set = w >> 3, grp = w & 7;   // ns GEMM role
    const int r0 = lane >> 2, r1 = r0 + 8;
    const int e0  = grp*8 + (lane & 3)*2;  // ns e-slice
    const int e0d = w*8   + (lane & 3)*2;  // d  e-slice
    const bool v0 = ((unsigned)(s0 - 1 + r0) < (unsigned)S);
    const bool v1 = ((unsigned)(s0 - 1 + r1) < (unsigned)S);

    uint* AnU = nsU;
    uint* AsU = nsU + 768;

    // head weights for this lane's e-slice (constant across steps)
    const float won0 = onW[e0d], won1 = onW[e0d+1];
    const float wos0 = osW[e0d], wos1 = osW[e0d+1];

    // per-warp B pointers (constant across steps)
    const uint4* BnsW = (set ? fBs4 : fBn4) + grp*64 + lane;  // +kt*512, +32 for half1
    const uint4* BdW  = fBd4 + w*64 + lane;                   // +kt*1024, +32 for half1

    // register-resident c-states (static lane ownership)
    float creg[4] = {0.f, 0.f, 0.f, 0.f};   // cn (warps 0-7) / cs (warps 8-15)
    float cd[4]   = {0.f, 0.f, 0.f, 0.f};

    for (int i = tid; i < 1536; i += TPB) nsU[i] = 0;
    for (int i = tid; i < 2048; i += TPB) adU[i] = 0;
    __syncthreads();

    for (int t = 0; t < NSTEP; ++t) {
        // ---- P0: neighbor waits, halo imports, xin, head-bias init ----
        if (t > 0) {
            if (tid == 0 && tile > 0) {
                volatile int* f = &g_flag[bb*NTILE + tile - 1];
                while (*f < t) {}
                __threadfence();
            }
            if (tid == 32 && tile < NTILE-1) {
                volatile int* f = &g_flag[bb*NTILE + tile + 1];
                while (*f < t) {}
                __threadfence();
            }
        }
        __syncthreads();

        if (t > 0) {
            const int pb = (t - 1) & 1;
            if (tile > 0) {  // left neighbor slot1 = site s0-2
                const float* L = g_pub[pb][bb][tile-1][1];
                for (int e = tid; e < 64; e += TPB) {
                    store_frag8(AnU, 0, 128+e, L[e]);
                    store_frag8(AsU, 0, 128+e, L[64+e]);
                }
                for (int e = tid - 64; ((unsigned)e) < 128u; e += TPB)
                    store_frag8(adU, 0, 384+e, L[128+e]);
            }
            if (tile < NTILE-1) {  // right neighbor slot0 = site s0+15
                const float* R = g_pub[pb][bb][tile+1][0];
                for (int e = tid - 192; ((unsigned)e) < 64u; e += TPB) {
                    store_frag8(AnU, 15, 64+e, R[e]);
                    store_frag8(AsU, 15, 64+e, R[64+e]);
                }
                for (int e = tid - 256; ((unsigned)e) < 128u; e += TPB)
                    store_frag8(adU, 15, 256+e, R[128+e]);
            }
        }
        for (int i = tid - 384; ((unsigned)i) < (unsigned)(NS*4); i += TPB) {
            int r = i >> 2, sg = s0 - 1 + r;
            xin[i] = ((unsigned)sg < (unsigned)S)
                     ? xg[(((size_t)bb*T + t)*S + sg)*4 + (i & 3)] : 0.f;
        }
        if (tid >= 448 && tid < 464) {
            o0s[tid - 448] = onb[0];
            o1s[tid - 448] = osb[0];
        }
        __syncthreads();

        // ---- P1: ns mma (6 kt32) + d1 mma (kt 4..15) + ns cell (registers) ----
        float acc[4][4], dacc[4][4];
        #pragma unroll
        for (int j = 0; j < 4; j++)
            #pragma unroll
            for (int c = 0; c < 4; c++) { acc[j][c] = 0.f; dacc[j][c] = 0.f; }
        {
            const uint4* A0 = nsF4 + set*192;
            for (int kt = 0; kt < 6; kt++) {
                uint4 a0 = A0[kt*32 + lane];
                uint4 u0 = __ldg(BnsW + kt*512);
                uint4 u1 = __ldg(BnsW + kt*512 + 32);
                MMA8(acc[0], a0.x, a0.y, a0.z, a0.w, u0.x, u0.y);
                MMA8(acc[1], a0.x, a0.y, a0.z, a0.w, u0.z, u0.w);
                MMA8(acc[2], a0.x, a0.y, a0.z, a0.w, u1.x, u1.y);
                MMA8(acc[3], a0.x, a0.y, a0.z, a0.w, u1.z, u1.w);
            }
            for (int kt = 4; kt < 16; kt++) {
                uint4 a0 = AdF4[kt*32 + lane];
                uint4 u0 = __ldg(BdW + kt*1024);
                uint4 u1 = __ldg(BdW + kt*1024 + 32);
                MMA8(dacc[0], a0.x, a0.y, a0.z, a0.w, u0.x, u0.y);
                MMA8(dacc[1], a0.x, a0.y, a0.z, a0.w, u0.z, u0.w);
                MMA8(dacc[2], a0.x, a0.y, a0.z, a0.w, u1.x, u1.y);
                MMA8(dacc[3], a0.x, a0.y, a0.z, a0.w, u1.z, u1.w);
            }
        }
        // rescale, x-input + bias fold (fp32 exact), cell update in registers
        float hv[4];
        {
            float xA[4], xB[4];
            #pragma unroll
            for (int k = 0; k < 4; k++) { xA[k] = xin[r0*4 + k]; xB[k] = xin[r1*4 + k]; }
            if (set == 0) {
                #pragma unroll
                for (int g = 0; g < 4; g++) {
                    int col = g*64 + e0;
                    float2 b2 = *(const float2*)&nb[col];
                    float2 w0 = *(const float2*)&nWx[col];
                    float2 w1 = *(const float2*)&nWx[256 + col];
                    float2 w2 = *(const float2*)&nWx[512 + col];
                    acc[g][0] = acc[g][0]*WISCALE + b2.x + xA[0]*w0.x + xA[1]*w1.x + xA[2]*w2.x;
                    acc[g][1] = acc[g][1]*WISCALE + b2.y + xA[0]*w0.y + xA[1]*w1.y + xA[2]*w2.y;
                    acc[g][2] = acc[g][2]*WISCALE + b2.x + xB[0]*w0.x + xB[1]*w1.x + xB[2]*w2.x;
                    acc[g][3] = acc[g][3]*WISCALE + b2.y + xB[0]*w0.y + xB[1]*w1.y + xB[2]*w2.y;
                }
            } else {
                #pragma unroll
                for (int g = 0; g < 4; g++) {
                    int col = g*64 + e0;
                    float2 b2 = *(const float2*)&sb[col];
                    float2 w3 = *(const float2*)&sWx[col];
                    acc[g][0] = acc[g][0]*WISCALE + b2.x + xA[3]*w3.x;
                    acc[g][1] = acc[g][1]*WISCALE + b2.y + xA[3]*w3.y;
                    acc[g][2] = acc[g][2]*WISCALE + b2.x + xB[3]*w3.x;
                    acc[g][3] = acc[g][3]*WISCALE + b2.y + xB[3]*w3.y;
                }
            }
            #pragma unroll
            for (int c = 0; c < 4; c++) {
                bool v = (c < 2) ? v0 : v1;
                float c2 = sigm(acc[1][c])*creg[c] + sigm(acc[0][c])*tanhap(acc[2][c]);
                float hh = sigm(acc[3][c])*tanhap(c2);
                if (!v) { c2 = 0.f; hh = 0.f; }
                creg[c] = c2;
                hv[c] = hh;
            }
            // current-step d A-matrix (k<128): k = set*64 + e
            store_fragp8(adU, r0, set*64 + e0, packe2(hv[0], hv[1]));
            store_fragp8(adU, r1, set*64 + e0, packe2(hv[2], hv[3]));
            // boundary publish (n/s parts)
            if (r0 == 1)  { float* P = g_pub[t&1][bb][tile][0]; P[set*64 + e0] = hv[0]; P[set*64 + e0 + 1] = hv[1]; }
            if (r1 == 14) { float* P = g_pub[t&1][bb][tile][1]; P[set*64 + e0] = hv[2]; P[set*64 + e0 + 1] = hv[3]; }
        }
        __syncthreads();

        // ---- P2: d2 mma (kt 0..3) + d cell (regs) + frag stores + pubs ----
        for (int kt = 0; kt < 4; kt++) {
            uint4 a0 = AdF4[kt*32 + lane];
            uint4 u0 = __ldg(BdW + kt*1024);
            uint4 u1 = __ldg(BdW + kt*1024 + 32);
            MMA8(dacc[0], a0.x, a0.y, a0.z, a0.w, u0.x, u0.y);
            MMA8(dacc[1], a0.x, a0.y, a0.z, a0.w, u0.z, u0.w);
            MMA8(dacc[2], a0.x, a0.y, a0.z, a0.w, u1.x, u1.y);
            MMA8(dacc[3], a0.x, a0.y, a0.z, a0.w, u1.z, u1.w);
        }
        {
            #pragma unroll
            for (int g = 0; g < 4; g++) {
                float2 b2 = *(const float2*)&db[g*128 + e0d];
                dacc[g][0] = dacc[g][0]*WISCALE + b2.x;
                dacc[g][1] = dacc[g][1]*WISCALE + b2.y;
                dacc[g][2] = dacc[g][2]*WISCALE + b2.x;
                dacc[g][3] = dacc[g][3]*WISCALE + b2.y;
            }
            float hdv[4];
            #pragma unroll
            for (int c = 0; c < 4; c++) {
                bool v = (c < 2) ? v0 : v1;
                float c2 = sigm(dacc[1][c])*cd[c] + sigm(dacc[0][c])*tanhap(dacc[2][c]);
                float hh = sigm(dacc[3][c])*tanhap(c2);
                if (!v) { c2 = 0.f; hh = 0.f; }
                cd[c] = c2;
                hdv[c] = hh;
            }
            *(float2*)&hdc[r0*128 + e0d] = make_float2(hdv[0], hdv[1]);
            *(float2*)&hdc[r1*128 + e0d] = make_float2(hdv[2], hdv[3]);
            ushort p01 = packe2(hdv[0], hdv[1]);
            ushort p23 = packe2(hdv[2], hdv[3]);
            store_fragp8(adU, r0, 128 + e0d, p01);
            store_fragp8(adU, r1, 128 + e0d, p23);
            if (r0 >= 1)  store_fragp8(adU, r0 - 1, 256 + e0d, p01);
            store_fragp8(adU, r1 - 1, 256 + e0d, p23);
            store_fragp8(adU, r0 + 1, 384 + e0d, p01);
            if (r1 <= 14) store_fragp8(adU, r1 + 1, 384 + e0d, p23);
            if (r0 == 1)  { float* P = g_pub[t&1][bb][tile][0]; P[128 + e0d] = hdv[0]; P[128 + e0d + 1] = hdv[1]; }
            if (r1 == 14) { float* P = g_pub[t&1][bb][tile][1]; P[128 + e0d] = hdv[2]; P[128 + e0d + 1] = hdv[3]; }
            // next-step ns A fragments from hv
            ushort q01 = packe2(hv[0], hv[1]);
            ushort q23 = packe2(hv[2], hv[3]);
            uint* F = set ? AsU : AnU;
            store_fragp8(F, r0, e0, q01);
            store_fragp8(F, r1, e0, q23);
            if (r0 >= 1)  store_fragp8(F, r0 - 1, 64 + e0, q01);
            store_fragp8(F, r1 - 1, 64 + e0, q23);
            store_fragp8(F, r0 + 1, 128 + e0, q01);
            if (r1 <= 14) store_fragp8(F, r1 + 1, 128 + e0, q23);
        }
        __syncthreads();

        // flag release (all pubs of step t complete) — heads/outputs after
        if (tid == 0) {
            __threadfence();
            *(volatile int*)&g_flag[bb*NTILE + tile] = t + 1;
        }

        // ---- P3: output heads (after flag; off the neighbor critical path) ----
        for (int task = w; task < 32; task += 16) {
            int which = task >> 4;
            int r = task & 15;
            const float* W = which ? osW : onW;
            float a = 0.f;
            #pragma unroll
            for (int kk = lane; kk < DH; kk += 32) a += hdc[r*DH + kk] * W[kk];
            #pragma unroll
            for (int d = 16; d >= 1; d >>= 1) a += __shfl_xor_sync(0xffffffffu, a, d);
            if (lane == 0) {
                if (which) o1s[r] += a;
                else       o0s[r] += a;
            }
        }
        __syncthreads();

        // ---- P4: write outputs for t >= 20 ----
        if (t >= 20 && tid >= 1 && tid <= TS) {
            int rr = tid;
            int sg = s0 + rr - 1;
            if (sg < S) {
                float o0 = o0s[rr];
                float o1 = o1s[rr];
                float inflow, spd;
                if (sg == 0) {
                    inflow = xg[(((size_t)bb*T + (t+1))*S + 0)*4 + 1];
                    spd    = xg[(((size_t)bb*T + (t+1))*S + 0)*4 + 3];
                } else {
                    inflow = o0s[rr-1];
                    spd    = o1;
                }
                float numc = xin[rr*4 + 2] + inflow - o0;
                float* o = out + ((((size_t)bb*TOUT) + (t - 20))*S + sg)*4;
                o[0] = o0; o[1] = inflow; o[2] = numc; o[3] = spd;
            }
        }
        __syncthreads();
    }
}

extern "C" void kernel_launch(void* const* d_in, const int* in_sizes, int n_in,
                              void* d_out, int out_size) {
    const float* xg  = (const float*)d_in[0];
    const float* nWx = (const float*)d_in[1];
    const float* nWh = (const float*)d_in[2];
    const float* nWa = (const float*)d_in[3];
    const float* nWb = (const float*)d_in[4];
    const float* nb  = (const float*)d_in[5];
    const float* sWx = (const float*)d_in[6];
    const float* sWh = (const float*)d_in[7];
    const float* sWa = (const float*)d_in[8];
    const float* sWb = (const float*)d_in[9];
    const float* sb  = (const float*)d_in[10];
    const float* dWx = (const float*)d_in[11];
    const float* dWh = (const float*)d_in[12];
    const float* dWa = (const float*)d_in[13];
    const float* dWb = (const float*)d_in[14];
    const float* db  = (const float*)d_in[15];
    const float* onW = (const float*)d_in[16];
    const float* onb = (const float*)d_in[17];
    const float* osW = (const float*)d_in[18];
    const float* osb = (const float*)d_in[19];
    float* out = (float*)d_out;

    (void)in_sizes; (void)n_in; (void)out_size;

    const int smem_bytes = SMEM_FLOATS * (int)sizeof(float);
    cudaFuncSetAttribute(persistent_kernel,
                         cudaFuncAttributeMaxDynamicSharedMemorySize, smem_bytes);

    init_flags_kernel<<<1, 256>>>();
    int repack_threads = 16*16*2*32 + 2*6*8*2*32;
    repack_kernel<<<(repack_threads + 255) / 256, 256>>>(
        nWh, nWa, nWb, sWh, sWa, sWb, dWx, dWh, dWa, dWb);

    dim3 grid(NTILE, NB);
    persistent_kernel<<<grid, TPB, smem_bytes>>>(
        xg, nWx, nb, sWx, sb, db, onW, onb, osW, osb, out);
}

// round 15
// speedup vs baseline: 1.2069x; 1.2069x over previous
#include <cuda_runtime.h>
#include <cuda_bf16.h>
#include <cuda_fp16.h>
#include <cuda_fp8.h>
#include <math.h>

typedef unsigned int uint;

#define S 128
#define T 128
#define NB 16
#define NH 64
#define DH 128
#define TS 15
#define NS 16
#define NTILE 9
#define TPB 512
#define TOUT 107
#define NSTEP 127

#define WSCALE 64.0f
#define WISCALE 0.015625f

// Warp-major fragment-ordered fp8(e4m3) weights (scaled x64), gate-interleaved N.
// fBd4[(kt*16 + w)*32 + lane] = {j0,j1,j2,j3} packed words (each = 4 e4m3)
// fBn4/fBs4[(kt*8 + grp)*32 + lane] likewise
__device__ uint4 fBn4[12*8*32];
__device__ uint4 fBs4[12*8*32];
__device__ uint4 fBd4[32*16*32];

// Boundary publish ring: [buf][b][tile][slot][256]
// slot0 = site s0, slot1 = site s0+13; [0:64) hn, [64:128) hs, [128:256) hd
__device__ float g_pub[2][NB][NTILE][2][256];
__device__ int g_flag[NB*NTILE];

// ---- smem offsets (floats) ----
#define OFF_XIN 0                      // 64
#define OFF_O0  (OFF_XIN + 64)         // 16
#define OFF_O1  (OFF_O0 + 16)          // 16
#define OFF_NSF (OFF_O1 + 16)          // 3072 uints: An@0, As@1536
#define OFF_ADF (OFF_NSF + 3072)       // 4096 uints
#define SMEM_FLOATS (OFF_ADF + 4096)

#define MMA4(c, a0,a1,a2,a3, b0,b1) \
  asm volatile("mma.sync.aligned.m16n8k16.row.col.f32.f16.f16.f32 " \
    "{%0,%1,%2,%3}, {%4,%5,%6,%7}, {%8,%9}, {%0,%1,%2,%3};" \
    : "+f"(c[0]), "+f"(c[1]), "+f"(c[2]), "+f"(c[3]) \
    : "r"(a0), "r"(a1), "r"(a2), "r"(a3), "r"(b0), "r"(b1))

// expand 4 packed e4m3 -> two f16x2 registers (exact conversion)
__device__ __forceinline__ void cvt8(uint w, uint& b0, uint& b1) {
    asm("{\n\t"
        ".reg .b16 lo, hi;\n\t"
        "mov.b32 {lo, hi}, %2;\n\t"
        "cvt.rn.f16x2.e4m3x2 %0, lo;\n\t"
        "cvt.rn.f16x2.e4m3x2 %1, hi;\n\t"
        "}" : "=r"(b0), "=r"(b1) : "r"(w));
}

__device__ __forceinline__ float tanhap(float x) {
    float y;
    asm("tanh.approx.f32 %0, %1;" : "=f"(y) : "f"(x));
    return y;
}
__device__ __forceinline__ float sigm(float x) {
    return fmaf(tanhap(0.5f*x), 0.5f, 0.5f);
}

__device__ __forceinline__ uint packh2(float a, float b) {
    __half2 h = __floats2half2_rn(a, b);
    return *(uint*)&h;
}

// scalar f16 store into fragment-ordered array at logical (row r, col k)
__device__ __forceinline__ void store_frag(__half* Fb, int r, int k, float v) {
    int kt = k >> 4, ec = k & 15;
    int reg = ((ec >> 3) << 1) | (r >> 3);
    int ln  = ((r & 7) << 2) | ((ec & 7) >> 1);
    int idx = ((((kt << 5) + ln) << 2) + reg) * 2 + (ec & 1);
    Fb[idx] = __float2half_rn(v);
}
// packed pair store (k even): writes f16 elements (r,k) and (r,k+1)
__device__ __forceinline__ void store_frag2(uint* Fu, int r, int k, uint v) {
    int kt = k >> 4, ec = k & 15;
    int reg = ((ec >> 3) << 1) | (r >> 3);
    int ln  = ((r & 7) << 2) | ((ec & 7) >> 1);
    Fu[(((kt << 5) + ln) << 2) + reg] = v;
}

__device__ __forceinline__ uint pack8(float v0, float v1, float v2, float v3) {
    __nv_fp8_e4m3 a(v0 * WSCALE), b(v1 * WSCALE), c(v2 * WSCALE), d(v3 * WSCALE);
    return (uint)a.__x | ((uint)b.__x << 8) | ((uint)c.__x << 16) | ((uint)d.__x << 24);
}

__global__ void init_flags_kernel() {
    int i = blockIdx.x * blockDim.x + threadIdx.x;
    if (i < NB*NTILE) g_flag[i] = 0;
}

__global__ void repack_kernel(
    const float* __restrict__ nWh, const float* __restrict__ nWa, const float* __restrict__ nWb,
    const float* __restrict__ sWh, const float* __restrict__ sWa, const float* __restrict__ sWb,
    const float* __restrict__ dWx, const float* __restrict__ dWh,
    const float* __restrict__ dWa, const float* __restrict__ dWb)
{
    int idx = blockIdx.x * blockDim.x + threadIdx.x;
    if (idx < 32*16*32) {
        int lane = idx & 31, wq = (idx >> 5) & 15, kt = idx >> 9;
        int k0 = kt*16 + (lane & 3)*2;
        uint res[4];
        #pragma unroll
        for (int j = 0; j < 4; j++) {
            int nprime = (wq*4 + j)*8 + (lane >> 2);
            int e = ((nprime >> 5) << 3) | (nprime & 7);
            int g = (nprime >> 3) & 3;
            int n = g*128 + e;
            float v[4];
            #pragma unroll
            for (int jj = 0; jj < 4; jj++) {
                int kk = k0 + (jj >> 1)*8 + (jj & 1);
                float x;
                if      (kk < 128) x = dWx[kk*512 + n];
                else if (kk < 256) x = dWh[(kk-128)*512 + n];
                else if (kk < 384) x = dWa[(kk-256)*512 + n];
                else               x = dWb[(kk-384)*512 + n];
                v[jj] = x;
            }
            res[j] = pack8(v[0], v[1], v[2], v[3]);
        }
        fBd4[idx] = make_uint4(res[0], res[1], res[2], res[3]);
    }
    int idx2 = idx - 32*16*32;
    if (idx2 >= 0 && idx2 < 2*12*8*32) {
        int set = idx2 / (12*8*32);
        int e_ = idx2 % (12*8*32);
        int lane = e_ & 31, gq = (e_ >> 5) & 7, kt = e_ >> 8;
        int k0 = kt*16 + (lane & 3)*2;
        const float* Wh = set ? sWh : nWh;
        const float* Wa = set ? sWa : nWa;
        const float* Wb = set ? sWb : nWb;
        uint res[4];
        #pragma unroll
        for (int j = 0; j < 4; j++) {
            int nprime = (gq*4 + j)*8 + (lane >> 2);
            int e = ((nprime >> 5) << 3) | (nprime & 7);
            int g = (nprime >> 3) & 3;
            int n = g*64 + e;
            float v[4];
            #pragma unroll
            for (int jj = 0; jj < 4; jj++) {
                int kk = k0 + (jj >> 1)*8 + (jj & 1);
                float x;
                if      (kk < 64)  x = Wh[kk*256 + n];
                else if (kk < 128) x = Wa[(kk-64)*256 + n];
                else               x = Wb[(kk-128)*256 + n];
                v[jj] = x;
            }
            res[j] = pack8(v[0], v[1], v[2], v[3]);
        }
        (set ? fBs4 : fBn4)[e_] = make_uint4(res[0], res[1], res[2], res[3]);
    }
}

__global__ void __launch_bounds__(TPB, 1) persistent_kernel(
    const float* __restrict__ xg,
    const float* __restrict__ nWx, const float* __restrict__ nb,
    const float* __restrict__ sWx, const float* __restrict__ sb,
    const float* __restrict__ db,
    const float* __restrict__ onW, const float* __restrict__ onb,
    const float* __restrict__ osW, const float* __restrict__ osb,
    float* __restrict__ out)
{
    extern __shared__ float sm[];
    float* xin = sm + OFF_XIN;   // [16][4]
    float* o0s = sm + OFF_O0;
    float* o1s = sm + OFF_O1;
    uint*  nsU = (uint*)(sm + OFF_NSF);   // An@0 (1536), As@1536
    uint4* nsF4 = (uint4*)(sm + OFF_NSF);
    uint*  adU = (uint*)(sm + OFF_ADF);   // 4096
    uint4* AdF4 = (uint4*)(sm + OFF_ADF);

    const int tid  = threadIdx.x;
    const int w    = tid >> 5;
    const int lane = tid & 31;
    const int tile = blockIdx.x;
    const int bb   = blockIdx.y;
    const int s0   = tile * TS;

    const int set = w >> 3, grp = w & 7;   // ns GEMM role
    const int r0 = lane >> 2, r1 = r0 + 8;
    const int e0  = grp*8 + (lane & 3)*2;  // ns e-slice
    const int e0d = w*8   + (lane & 3)*2;  // d  e-slice
    const bool v0 = ((unsigned)(s0 - 1 + r0) < (unsigned)S);
    const bool v1 = ((unsigned)(s0 - 1 + r1) < (unsigned)S);

    __half* AnB = (__half*)nsU;
    __half* AsB = AnB + 3072;
    __half* AdB = (__half*)adU;
    uint* AnU = nsU;
    uint* AsU = nsU + 1536;

    // head weights for this lane's e-slice (constant across steps)
    const float won0 = onW[e0d], won1 = onW[e0d+1];
    const float wos0 = osW[e0d], wos1 = osW[e0d+1];

    // per-warp B pointers (constant across steps)
    const uint4* BnsW = (set ? fBs4 : fBn4) + grp*32 + lane;  // + kt*256
    const uint4* BdW  = fBd4 + w*32 + lane;                   // + kt*512

    // register-resident c-states (static lane ownership)
    float creg[4] = {0.f, 0.f, 0.f, 0.f};   // cn (warps 0-7) / cs (warps 8-15)
    float cd[4]   = {0.f, 0.f, 0.f, 0.f};

    for (int i = tid; i < 3072; i += TPB) nsU[i] = 0;
    for (int i = tid; i < 4096; i += TPB) adU[i] = 0;
    __syncthreads();

    for (int t = 0; t < NSTEP; ++t) {
        // ---- P0: neighbor waits, halo imports, xin, head-bias init ----
        if (t > 0) {
            if (tid == 0 && tile > 0) {
                volatile int* f = &g_flag[bb*NTILE + tile - 1];
                while (*f < t) {}
                __threadfence();
            }
            if (tid == 32 && tile < NTILE-1) {
                volatile int* f = &g_flag[bb*NTILE + tile + 1];
                while (*f < t) {}
                __threadfence();
            }
        }
        __syncthreads();

        if (t > 0) {
            const int pb = (t - 1) & 1;
            if (tile > 0) {  // left neighbor slot1 = site s0-2
                const float* L = g_pub[pb][bb][tile-1][1];
                for (int e = tid; e < 64; e += TPB) {
                    store_frag(AnB, 0, 128+e, L[e]);
                    store_frag(AsB, 0, 128+e, L[64+e]);
                }
                for (int e = tid - 64; ((unsigned)e) < 128u; e += TPB)
                    store_frag(AdB, 0, 384+e, L[128+e]);
            }
            if (tile < NTILE-1) {  // right neighbor slot0 = site s0+15
                const float* R = g_pub[pb][bb][tile+1][0];
                for (int e = tid - 192; ((unsigned)e) < 64u; e += TPB) {
                    store_frag(AnB, 15, 64+e, R[e]);
                    store_frag(AsB, 15, 64+e, R[64+e]);
                }
                for (int e = tid - 256; ((unsigned)e) < 128u; e += TPB)
                    store_frag(AdB, 15, 256+e, R[128+e]);
            }
        }
        for (int i = tid - 384; ((unsigned)i) < (unsigned)(NS*4); i += TPB) {
            int r = i >> 2, sg = s0 - 1 + r;
            xin[i] = ((unsigned)sg < (unsigned)S)
                     ? xg[(((size_t)bb*T + t)*S + sg)*4 + (i & 3)] : 0.f;
        }
        if (tid >= 448 && tid < 464) {
            o0s[tid - 448] = onb[0];
            o1s[tid - 448] = osb[0];
        }
        __syncthreads();

        // ---- P1: ns mma + d1 mma (one LDG.128 per kt) + ns cell ----
        float acc[4][4], dacc[4][4];
        #pragma unroll
        for (int j = 0; j < 4; j++)
            #pragma unroll
            for (int c = 0; c < 4; c++) { acc[j][c] = 0.f; dacc[j][c] = 0.f; }
        {
            const uint4* A0 = nsF4 + set*384;
            for (int kt = 0; kt < 12; kt++) {
                uint4 a0 = A0[kt*32 + lane];
                uint4 wv = __ldg(BnsW + kt*256);
                uint b0, b1;
                cvt8(wv.x, b0, b1); MMA4(acc[0], a0.x, a0.y, a0.z, a0.w, b0, b1);
                cvt8(wv.y, b0, b1); MMA4(acc[1], a0.x, a0.y, a0.z, a0.w, b0, b1);
                cvt8(wv.z, b0, b1); MMA4(acc[2], a0.x, a0.y, a0.z, a0.w, b0, b1);
                cvt8(wv.w, b0, b1); MMA4(acc[3], a0.x, a0.y, a0.z, a0.w, b0, b1);
            }
            for (int kt = 8; kt < 32; kt++) {
                uint4 a0 = AdF4[kt*32 + lane];
                uint4 wv = __ldg(BdW + kt*512);
                uint b0, b1;
                cvt8(wv.x, b0, b1); MMA4(dacc[0], a0.x, a0.y, a0.z, a0.w, b0, b1);
                cvt8(wv.y, b0, b1); MMA4(dacc[1], a0.x, a0.y, a0.z, a0.w, b0, b1);
                cvt8(wv.z, b0, b1); MMA4(dacc[2], a0.x, a0.y, a0.z, a0.w, b0, b1);
                cvt8(wv.w, b0, b1); MMA4(dacc[3], a0.x, a0.y, a0.z, a0.w, b0, b1);
            }
        }
        // rescale, x-input + bias fold (fp32 exact), cell update in registers
        float hv[4];
        {
            float xA[4], xB[4];
            #pragma unroll
            for (int k = 0; k < 4; k++) { xA[k] = xin[r0*4 + k]; xB[k] = xin[r1*4 + k]; }
            if (set == 0) {
                #pragma unroll
                for (int g = 0; g < 4; g++) {
                    int col = g*64 + e0;
                    float2 b2 = *(const float2*)&nb[col];
                    float2 w0 = *(const float2*)&nWx[col];
                    float2 w1 = *(const float2*)&nWx[256 + col];
                    float2 w2 = *(const float2*)&nWx[512 + col];
                    acc[g][0] = acc[g][0]*WISCALE + b2.x + xA[0]*w0.x + xA[1]*w1.x + xA[2]*w2.x;
                    acc[g][1] = acc[g][1]*WISCALE + b2.y + xA[0]*w0.y + xA[1]*w1.y + xA[2]*w2.y;
                    acc[g][2] = acc[g][2]*WISCALE + b2.x + xB[0]*w0.x + xB[1]*w1.x + xB[2]*w2.x;
                    acc[g][3] = acc[g][3]*WISCALE + b2.y + xB[0]*w0.y + xB[1]*w1.y + xB[2]*w2.y;
                }
            } else {
                #pragma unroll
                for (int g = 0; g < 4; g++) {
                    int col = g*64 + e0;
                    float2 b2 = *(const float2*)&sb[col];
                    float2 w3 = *(const float2*)&sWx[col];
                    acc[g][0] = acc[g][0]*WISCALE + b2.x + xA[3]*w3.x;
                    acc[g][1] = acc[g][1]*WISCALE + b2.y + xA[3]*w3.y;
                    acc[g][2] = acc[g][2]*WISCALE + b2.x + xB[3]*w3.x;
                    acc[g][3] = acc[g][3]*WISCALE + b2.y + xB[3]*w3.y;
                }
            }
            #pragma unroll
            for (int c = 0; c < 4; c++) {
                bool v = (c < 2) ? v0 : v1;
                float c2 = sigm(acc[1][c])*creg[c] + sigm(acc[0][c])*tanhap(acc[2][c]);
                float hh = sigm(acc[3][c])*tanhap(c2);
                if (!v) { c2 = 0.f; hh = 0.f; }
                creg[c] = c2;
                hv[c] = hh;
            }
            // current-step d A-matrix (kt 0..7): k = set*64 + e
            store_frag2(adU, r0, set*64 + e0, packh2(hv[0], hv[1]));
            store_frag2(adU, r1, set*64 + e0, packh2(hv[2], hv[3]));
            // boundary publish (n/s parts)
            if (r0 == 1)  { float* P = g_pub[t&1][bb][tile][0]; P[set*64 + e0] = hv[0]; P[set*64 + e0 + 1] = hv[1]; }
            if (r1 == 14) { float* P = g_pub[t&1][bb][tile][1]; P[set*64 + e0] = hv[2]; P[set*64 + e0 + 1] = hv[3]; }
        }
        __syncthreads();

        // ---- P2: d2 mma + d cell (regs) + frag stores + pubs + in-reg heads ----
        for (int kt = 0; kt < 8; kt++) {
            uint4 a0 = AdF4[kt*32 + lane];
            uint4 wv = __ldg(BdW + kt*512);
            uint b0, b1;
            cvt8(wv.x, b0, b1); MMA4(dacc[0], a0.x, a0.y, a0.z, a0.w, b0, b1);
            cvt8(wv.y, b0, b1); MMA4(dacc[1], a0.x, a0.y, a0.z, a0.w, b0, b1);
            cvt8(wv.z, b0, b1); MMA4(dacc[2], a0.x, a0.y, a0.z, a0.w, b0, b1);
            cvt8(wv.w, b0, b1); MMA4(dacc[3], a0.x, a0.y, a0.z, a0.w, b0, b1);
        }
        {
            #pragma unroll
            for (int g = 0; g < 4; g++) {
                float2 b2 = *(const float2*)&db[g*128 + e0d];
                dacc[g][0] = dacc[g][0]*WISCALE + b2.x;
                dacc[g][1] = dacc[g][1]*WISCALE + b2.y;
                dacc[g][2] = dacc[g][2]*WISCALE + b2.x;
                dacc[g][3] = dacc[g][3]*WISCALE + b2.y;
            }
            float hdv[4];
            #pragma unroll
            for (int c = 0; c < 4; c++) {
                bool v = (c < 2) ? v0 : v1;
                float c2 = sigm(dacc[1][c])*cd[c] + sigm(dacc[0][c])*tanhap(dacc[2][c]);
                float hh = sigm(dacc[3][c])*tanhap(c2);
                if (!v) { c2 = 0.f; hh = 0.f; }
                cd[c] = c2;
                hdv[c] = hh;
            }
            uint p01 = packh2(hdv[0], hdv[1]);
            uint p23 = packh2(hdv[2], hdv[3]);
            store_frag2(adU, r0, 128 + e0d, p01);
            store_frag2(adU, r1, 128 + e0d, p23);
            if (r0 >= 1)  store_frag2(adU, r0 - 1, 256 + e0d, p01);
            store_frag2(adU, r1 - 1, 256 + e0d, p23);
            store_frag2(adU, r0 + 1, 384 + e0d, p01);
            if (r1 <= 14) store_frag2(adU, r1 + 1, 384 + e0d, p23);
            if (r0 == 1)  { float* P = g_pub[t&1][bb][tile][0]; P[128 + e0d] = hdv[0]; P[128 + e0d + 1] = hdv[1]; }
            if (r1 == 14) { float* P = g_pub[t&1][bb][tile][1]; P[128 + e0d] = hdv[2]; P[128 + e0d + 1] = hdv[3]; }
            // next-step ns A fragments from hv
            uint q01 = packh2(hv[0], hv[1]);
            uint q23 = packh2(hv[2], hv[3]);
            uint* F = set ? AsU : AnU;
            store_frag2(F, r0, e0, q01);
            store_frag2(F, r1, e0, q23);
            if (r0 >= 1)  store_frag2(F, r0 - 1, 64 + e0, q01);
            store_frag2(F, r1 - 1, 64 + e0, q23);
            store_frag2(F, r0 + 1, 128 + e0, q01);
            if (r1 <= 14) store_frag2(F, r1 + 1, 128 + e0, q23);
            // in-register output heads: quad reduce + smem atomics
            float p0 = hdv[0]*won0 + hdv[1]*won1;
            float p1 = hdv[2]*won0 + hdv[3]*won1;
            float q0 = hdv[0]*wos0 + hdv[1]*wos1;
            float q1 = hdv[2]*wos0 + hdv[3]*wos1;
            p0 += __shfl_xor_sync(0xffffffffu, p0, 1);
            p0 += __shfl_xor_sync(0xffffffffu, p0, 2);
            p1 += __shfl_xor_sync(0xffffffffu, p1, 1);
            p1 += __shfl_xor_sync(0xffffffffu, p1, 2);
            q0 += __shfl_xor_sync(0xffffffffu, q0, 1);
            q0 += __shfl_xor_sync(0xffffffffu, q0, 2);
            q1 += __shfl_xor_sync(0xffffffffu, q1, 1);
            q1 += __shfl_xor_sync(0xffffffffu, q1, 2);
            if ((lane & 3) == 0) {
                atomicAdd(&o0s[r0], p0); atomicAdd(&o0s[r1], p1);
                atomicAdd(&o1s[r0], q0); atomicAdd(&o1s[r1], q1);
            }
        }
        __syncthreads();

        // flag release (all pubs of step t complete)
        if (tid == 0) {
            __threadfence();
            *(volatile int*)&g_flag[bb*NTILE + tile] = t + 1;
        }

        // ---- P3: write outputs for t >= 20 ----
        if (t >= 20 && tid >= 1 && tid <= TS) {
            int rr = tid;
            int sg = s0 + rr - 1;
            if (sg < S) {
                float o0 = o0s[rr];
                float o1 = o1s[rr];
                float inflow, spd;
                if (sg == 0) {
                    inflow = xg[(((size_t)bb*T + (t+1))*S + 0)*4 + 1];
                    spd    = xg[(((size_t)bb*T + (t+1))*S + 0)*4 + 3];
                } else {
                    inflow = o0s[rr-1];
                    spd    = o1;
                }
                float numc = xin[rr*4 + 2] + inflow - o0;
                float* o = out + ((((size_t)bb*TOUT) + (t - 20))*S + sg)*4;
                o[0] = o0; o[1] = inflow; o[2] = numc; o[3] = spd;
            }
        }
        __syncthreads();
    }
}

extern "C" void kernel_launch(void* const* d_in, const int* in_sizes, int n_in,
                              void* d_out, int out_size) {
    const float* xg  = (const float*)d_in[0];
    const float* nWx = (const float*)d_in[1];
    const float* nWh = (const float*)d_in[2];
    const float* nWa = (const float*)d_in[3];
    const float* nWb = (const float*)d_in[4];
    const float* nb  = (const float*)d_in[5];
    const float* sWx = (const float*)d_in[6];
    const float* sWh = (const float*)d_in[7];
    const float* sWa = (const float*)d_in[8];
    const float* sWb = (const float*)d_in[9];
    const float* sb  = (const float*)d_in[10];
    const float* dWx = (const float*)d_in[11];
    const float* dWh = (const float*)d_in[12];
    const float* dWa = (const float*)d_in[13];
    const float* dWb = (const float*)d_in[14];
    const float* db  = (const float*)d_in[15];
    const float* onW = (const float*)d_in[16];
    const float* onb = (const float*)d_in[17];
    const float* osW = (const float*)d_in[18];
    const float* osb = (const float*)d_in[19];
    float* out = (float*)d_out;

    (void)in_sizes; (void)n_in; (void)out_size;

    const int smem_bytes = SMEM_FLOATS * (int)sizeof(float);
    cudaFuncSetAttribute(persistent_kernel,
                         cudaFuncAttributeMaxDynamicSharedMemorySize, smem_bytes);

    init_flags_kernel<<<1, 256>>>();
    int repack_threads = 32*16*32 + 2*12*8*32;
    repack_kernel<<<(repack_threads + 255) / 256, 256>>>(
        nWh, nWa, nWb, sWh, sWa, sWb, dWx, dWh, dWa, dWb);

    dim3 grid(NTILE, NB);
    persistent_kernel<<<grid, TPB, smem_bytes>>>(
        xg, nWx, nb, sWx, sb, db, onW, onb, osW, osb, out);
}

// round 16
// speedup vs baseline: 1.4301x; 1.1850x over previous
#include <cuda_runtime.h>
#include <cuda_bf16.h>
#include <cuda_fp16.h>
#include <cuda_fp8.h>
#include <math.h>

typedef unsigned int uint;

#define S 128
#define T 128
#define NB 16
#define NH 64
#define DH 128
#define TS 15
#define NS 16
#define NTILE 9
#define TPB 512
#define TOUT 107
#define NSTEP 127

#define WSCALE 64.0f
#define WISCALE 0.015625f

// Warp-major fragment-ordered fp8(e4m3) weights (scaled x64), gate-interleaved N.
// fBd4[(kt*16 + w)*32 + lane] = {j0,j1,j2,j3} packed words (each = 4 e4m3)
// fBn4/fBs4[(kt*8 + grp)*32 + lane] likewise
__device__ uint4 fBn4[12*8*32];
__device__ uint4 fBs4[12*8*32];
__device__ uint4 fBd4[32*16*32];

// Boundary publish ring: [buf][b][tile][slot][256]
// slot0 = site s0, slot1 = site s0+13; [0:64) hn, [64:128) hs, [128:256) hd
__device__ float g_pub[2][NB][NTILE][2][256];
__device__ int g_flag[NB*NTILE];

// ---- smem offsets (floats) ----
#define OFF_XIN 0                      // 64
#define OFF_HDC (OFF_XIN + 64)         // 2048
#define OFF_NSF (OFF_HDC + 2048)       // 3072 uints: An@0, As@1536
#define OFF_ADF (OFF_NSF + 3072)       // 4096 uints
#define SMEM_FLOATS (OFF_ADF + 4096)

#define MMA4(c, a0,a1,a2,a3, b0,b1) \
  asm volatile("mma.sync.aligned.m16n8k16.row.col.f32.f16.f16.f32 " \
    "{%0,%1,%2,%3}, {%4,%5,%6,%7}, {%8,%9}, {%0,%1,%2,%3};" \
    : "+f"(c[0]), "+f"(c[1]), "+f"(c[2]), "+f"(c[3]) \
    : "r"(a0), "r"(a1), "r"(a2), "r"(a3), "r"(b0), "r"(b1))

// expand 4 packed e4m3 -> two f16x2 registers (exact conversion)
__device__ __forceinline__ void cvt8(uint w, uint& b0, uint& b1) {
    asm("{\n\t"
        ".reg .b16 lo, hi;\n\t"
        "mov.b32 {lo, hi}, %2;\n\t"
        "cvt.rn.f16x2.e4m3x2 %0, lo;\n\t"
        "cvt.rn.f16x2.e4m3x2 %1, hi;\n\t"
        "}" : "=r"(b0), "=r"(b1) : "r"(w));
}

__device__ __forceinline__ float tanhap(float x) {
    float y;
    asm("tanh.approx.f32 %0, %1;" : "=f"(y) : "f"(x));
    return y;
}
__device__ __forceinline__ float sigm(float x) {
    return fmaf(tanhap(0.5f*x), 0.5f, 0.5f);
}

__device__ __forceinline__ uint packh2(float a, float b) {
    __half2 h = __floats2half2_rn(a, b);
    return *(uint*)&h;
}

// scalar f16 store into fragment-ordered array at logical (row r, col k)
__device__ __forceinline__ void store_frag(__half* Fb, int r, int k, float v) {
    int kt = k >> 4, ec = k & 15;
    int reg = ((ec >> 3) << 1) | (r >> 3);
    int ln  = ((r & 7) << 2) | ((ec & 7) >> 1);
    int idx = ((((kt << 5) + ln) << 2) + reg) * 2 + (ec & 1);
    Fb[idx] = __float2half_rn(v);
}
// packed pair store (k even): writes f16 elements (r,k) and (r,k+1)
__device__ __forceinline__ void store_frag2(uint* Fu, int r, int k, uint v) {
    int kt = k >> 4, ec = k & 15;
    int reg = ((ec >> 3) << 1) | (r >> 3);
    int ln  = ((r & 7) << 2) | ((ec & 7) >> 1);
    Fu[(((kt << 5) + ln) << 2) + reg] = v;
}

__device__ __forceinline__ uint pack8(float v0, float v1, float v2, float v3) {
    __nv_fp8_e4m3 a(v0 * WSCALE), b(v1 * WSCALE), c(v2 * WSCALE), d(v3 * WSCALE);
    return (uint)a.__x | ((uint)b.__x << 8) | ((uint)c.__x << 16) | ((uint)d.__x << 24);
}

__global__ void init_flags_kernel() {
    int i = blockIdx.x * blockDim.x + threadIdx.x;
    if (i < NB*NTILE) g_flag[i] = 0;
}

__global__ void repack_kernel(
    const float* __restrict__ nWh, const float* __restrict__ nWa, const float* __restrict__ nWb,
    const float* __restrict__ sWh, const float* __restrict__ sWa, const float* __restrict__ sWb,
    const float* __restrict__ dWx, const float* __restrict__ dWh,
    const float* __restrict__ dWa, const float* __restrict__ dWb)
{
    int idx = blockIdx.x * blockDim.x + threadIdx.x;
    if (idx < 32*16*32) {
        int lane = idx & 31, wq = (idx >> 5) & 15, kt = idx >> 9;
        int k0 = kt*16 + (lane & 3)*2;
        uint res[4];
        #pragma unroll
        for (int j = 0; j < 4; j++) {
            int nprime = (wq*4 + j)*8 + (lane >> 2);
            int e = ((nprime >> 5) << 3) | (nprime & 7);
            int g = (nprime >> 3) & 3;
            int n = g*128 + e;
            float v[4];
            #pragma unroll
            for (int jj = 0; jj < 4; jj++) {
                int kk = k0 + (jj >> 1)*8 + (jj & 1);
                float x;
                if      (kk < 128) x = dWx[kk*512 + n];
                else if (kk < 256) x = dWh[(kk-128)*512 + n];
                else if (kk < 384) x = dWa[(kk-256)*512 + n];
                else               x = dWb[(kk-384)*512 + n];
                v[jj] = x;
            }
            res[j] = pack8(v[0], v[1], v[2], v[3]);
        }
        fBd4[idx] = make_uint4(res[0], res[1], res[2], res[3]);
    }
    int idx2 = idx - 32*16*32;
    if (idx2 >= 0 && idx2 < 2*12*8*32) {
        int set = idx2 / (12*8*32);
        int e_ = idx2 % (12*8*32);
        int lane = e_ & 31, gq = (e_ >> 5) & 7, kt = e_ >> 8;
        int k0 = kt*16 + (lane & 3)*2;
        const float* Wh = set ? sWh : nWh;
        const float* Wa = set ? sWa : nWa;
        const float* Wb = set ? sWb : nWb;
        uint res[4];
        #pragma unroll
        for (int j = 0; j < 4; j++) {
            int nprime = (gq*4 + j)*8 + (lane >> 2);
            int e = ((nprime >> 5) << 3) | (nprime & 7);
            int g = (nprime >> 3) & 3;
            int n = g*64 + e;
            float v[4];
            #pragma unroll
            for (int jj = 0; jj < 4; jj++) {
                int kk = k0 + (jj >> 1)*8 + (jj & 1);
                float x;
                if      (kk < 64)  x = Wh[kk*256 + n];
                else if (kk < 128) x = Wa[(kk-64)*256 + n];
                else               x = Wb[(kk-128)*256 + n];
                v[jj] = x;
            }
            res[j] = pack8(v[0], v[1], v[2], v[3]);
        }
        (set ? fBs4 : fBn4)[e_] = make_uint4(res[0], res[1], res[2], res[3]);
    }
}

__global__ void __launch_bounds__(TPB, 1) persistent_kernel(
    const float* __restrict__ xg,
    const float* __restrict__ nWx, const float* __restrict__ nb,
    const float* __restrict__ sWx, const float* __restrict__ sb,
    const float* __restrict__ db,
    const float* __restrict__ onW, const float* __restrict__ onb,
    const float* __restrict__ osW, const float* __restrict__ osb,
    float* __restrict__ out)
{
    extern __shared__ float sm[];
    float* xin = sm + OFF_XIN;   // [16][4]
    float* hdc = sm + OFF_HDC;   // [16*128]
    uint*  nsU = (uint*)(sm + OFF_NSF);   // An@0 (1536), As@1536
    uint4* nsF4 = (uint4*)(sm + OFF_NSF);
    uint*  adU = (uint*)(sm + OFF_ADF);   // 4096
    uint4* AdF4 = (uint4*)(sm + OFF_ADF);

    const int tid  = threadIdx.x;
    const int w    = tid >> 5;
    const int lane = tid & 31;
    const int tile = blockIdx.x;
    const int bb   = blockIdx.y;
    const int s0   = tile * TS;

    const int set = w >> 3, grp = w & 7;   // ns GEMM role
    const int r0 = lane >> 2, r1 = r0 + 8;
    const int e0  = grp*8 + (lane & 3)*2;  // ns e-slice
    const int e0d = w*8   + (lane & 3)*2;  // d  e-slice
    const bool v0 = ((unsigned)(s0 - 1 + r0) < (unsigned)S);
    const bool v1 = ((unsigned)(s0 - 1 + r1) < (unsigned)S);

    __half* AnB = (__half*)nsU;
    __half* AsB = AnB + 3072;
    __half* AdB = (__half*)adU;
    uint* AnU = nsU;
    uint* AsU = nsU + 1536;

    // per-warp B pointers (constant across steps)
    const uint4* BnsW = (set ? fBs4 : fBn4) + grp*32 + lane;  // + kt*256
    const uint4* BdW  = fBd4 + w*32 + lane;                   // + kt*512

    // register-resident c-states (static lane ownership)
    float creg[4] = {0.f, 0.f, 0.f, 0.f};   // cn (warps 0-7) / cs (warps 8-15)
    float cd[4]   = {0.f, 0.f, 0.f, 0.f};

    for (int i = tid; i < 3072; i += TPB) nsU[i] = 0;
    for (int i = tid; i < 4096; i += TPB) adU[i] = 0;
    __syncthreads();

    for (int t = 0; t < NSTEP; ++t) {
        // ---- Phase A: halo-free d mma (kt 8..15, prev-step local hd) ----
        float dacc[4][4];
        #pragma unroll
        for (int j = 0; j < 4; j++)
            #pragma unroll
            for (int c = 0; c < 4; c++) dacc[j][c] = 0.f;
        #pragma unroll 2
        for (int kt = 8; kt < 16; kt++) {
            uint4 a0 = AdF4[kt*32 + lane];
            uint4 wv = __ldg(BdW + kt*512);
            uint b0, b1;
            cvt8(wv.x, b0, b1); MMA4(dacc[0], a0.x, a0.y, a0.z, a0.w, b0, b1);
            cvt8(wv.y, b0, b1); MMA4(dacc[1], a0.x, a0.y, a0.z, a0.w, b0, b1);
            cvt8(wv.z, b0, b1); MMA4(dacc[2], a0.x, a0.y, a0.z, a0.w, b0, b1);
            cvt8(wv.w, b0, b1); MMA4(dacc[3], a0.x, a0.y, a0.z, a0.w, b0, b1);
        }
        // neighbor flag waits (overlapped with the mma above)
        if (t > 0) {
            if (tid == 0 && tile > 0) {
                volatile int* f = &g_flag[bb*NTILE + tile - 1];
                while (*f < t) {}
                __threadfence();
            }
            if (tid == 32 && tile < NTILE-1) {
                volatile int* f = &g_flag[bb*NTILE + tile + 1];
                while (*f < t) {}
                __threadfence();
            }
        }
        __syncthreads();

        // ---- Phase B: halo imports + xin ----
        if (t > 0) {
            const int pb = (t - 1) & 1;
            if (tile > 0) {  // left neighbor slot1 = site s0-2
                const float* L = g_pub[pb][bb][tile-1][1];
                for (int e = tid; e < 64; e += TPB) {
                    store_frag(AnB, 0, 128+e, L[e]);
                    store_frag(AsB, 0, 128+e, L[64+e]);
                }
                for (int e = tid - 64; ((unsigned)e) < 128u; e += TPB)
                    store_frag(AdB, 0, 384+e, L[128+e]);
            }
            if (tile < NTILE-1) {  // right neighbor slot0 = site s0+15
                const float* R = g_pub[pb][bb][tile+1][0];
                for (int e = tid - 192; ((unsigned)e) < 64u; e += TPB) {
                    store_frag(AnB, 15, 64+e, R[e]);
                    store_frag(AsB, 15, 64+e, R[64+e]);
                }
                for (int e = tid - 256; ((unsigned)e) < 128u; e += TPB)
                    store_frag(AdB, 15, 256+e, R[128+e]);
            }
        }
        for (int i = tid - 384; ((unsigned)i) < (unsigned)(NS*4); i += TPB) {
            int r = i >> 2, sg = s0 - 1 + r;
            xin[i] = ((unsigned)sg < (unsigned)S)
                     ? xg[(((size_t)bb*T + t)*S + sg)*4 + (i & 3)] : 0.f;
        }
        __syncthreads();

        // ---- Phase C: ns mma (kt 0..11) + d mma (kt 16..31) + ns cell ----
        float acc[4][4];
        #pragma unroll
        for (int j = 0; j < 4; j++)
            #pragma unroll
            for (int c = 0; c < 4; c++) acc[j][c] = 0.f;
        {
            const uint4* A0 = nsF4 + set*384;
            for (int kt = 0; kt < 12; kt++) {
                uint4 a0 = A0[kt*32 + lane];
                uint4 wv = __ldg(BnsW + kt*256);
                uint b0, b1;
                cvt8(wv.x, b0, b1); MMA4(acc[0], a0.x, a0.y, a0.z, a0.w, b0, b1);
                cvt8(wv.y, b0, b1); MMA4(acc[1], a0.x, a0.y, a0.z, a0.w, b0, b1);
                cvt8(wv.z, b0, b1); MMA4(acc[2], a0.x, a0.y, a0.z, a0.w, b0, b1);
                cvt8(wv.w, b0, b1); MMA4(acc[3], a0.x, a0.y, a0.z, a0.w, b0, b1);
            }
            for (int kt = 16; kt < 32; kt++) {
                uint4 a0 = AdF4[kt*32 + lane];
                uint4 wv = __ldg(BdW + kt*512);
                uint b0, b1;
                cvt8(wv.x, b0, b1); MMA4(dacc[0], a0.x, a0.y, a0.z, a0.w, b0, b1);
                cvt8(wv.y, b0, b1); MMA4(dacc[1], a0.x, a0.y, a0.z, a0.w, b0, b1);
                cvt8(wv.z, b0, b1); MMA4(dacc[2], a0.x, a0.y, a0.z, a0.w, b0, b1);
                cvt8(wv.w, b0, b1); MMA4(dacc[3], a0.x, a0.y, a0.z, a0.w, b0, b1);
            }
        }
        // rescale, x-input + bias fold (fp32 exact), cell update in registers
        float hv[4];
        {
            float xA[4], xB[4];
            #pragma unroll
            for (int k = 0; k < 4; k++) { xA[k] = xin[r0*4 + k]; xB[k] = xin[r1*4 + k]; }
            if (set == 0) {
                #pragma unroll
                for (int g = 0; g < 4; g++) {
                    int col = g*64 + e0;
                    float2 b2 = *(const float2*)&nb[col];
                    float2 w0 = *(const float2*)&nWx[col];
                    float2 w1 = *(const float2*)&nWx[256 + col];
                    float2 w2 = *(const float2*)&nWx[512 + col];
                    acc[g][0] = acc[g][0]*WISCALE + b2.x + xA[0]*w0.x + xA[1]*w1.x + xA[2]*w2.x;
                    acc[g][1] = acc[g][1]*WISCALE + b2.y + xA[0]*w0.y + xA[1]*w1.y + xA[2]*w2.y;
                    acc[g][2] = acc[g][2]*WISCALE + b2.x + xB[0]*w0.x + xB[1]*w1.x + xB[2]*w2.x;
                    acc[g][3] = acc[g][3]*WISCALE + b2.y + xB[0]*w0.y + xB[1]*w1.y + xB[2]*w2.y;
                }
            } else {
                #pragma unroll
                for (int g = 0; g < 4; g++) {
                    int col = g*64 + e0;
                    float2 b2 = *(const float2*)&sb[col];
                    float2 w3 = *(const float2*)&sWx[col];
                    acc[g][0] = acc[g][0]*WISCALE + b2.x + xA[3]*w3.x;
                    acc[g][1] = acc[g][1]*WISCALE + b2.y + xA[3]*w3.y;
                    acc[g][2] = acc[g][2]*WISCALE + b2.x + xB[3]*w3.x;
                    acc[g][3] = acc[g][3]*WISCALE + b2.y + xB[3]*w3.y;
                }
            }
            #pragma unroll
            for (int c = 0; c < 4; c++) {
                bool v = (c < 2) ? v0 : v1;
                float c2 = sigm(acc[1][c])*creg[c] + sigm(acc[0][c])*tanhap(acc[2][c]);
                float hh = sigm(acc[3][c])*tanhap(c2);
                if (!v) { c2 = 0.f; hh = 0.f; }
                creg[c] = c2;
                hv[c] = hh;
            }
            // current-step d A-matrix (kt 0..7): k = set*64 + e
            store_frag2(adU, r0, set*64 + e0, packh2(hv[0], hv[1]));
            store_frag2(adU, r1, set*64 + e0, packh2(hv[2], hv[3]));
            // boundary publish (n/s parts)
            if (r0 == 1)  { float* P = g_pub[t&1][bb][tile][0]; P[set*64 + e0] = hv[0]; P[set*64 + e0 + 1] = hv[1]; }
            if (r1 == 14) { float* P = g_pub[t&1][bb][tile][1]; P[set*64 + e0] = hv[2]; P[set*64 + e0 + 1] = hv[3]; }
        }
        __syncthreads();

        // ---- Phase D: d mma (kt 0..7) + d cell (regs) + frag stores + pubs ----
        #pragma unroll 2
        for (int kt = 0; kt < 8; kt++) {
            uint4 a0 = AdF4[kt*32 + lane];
            uint4 wv = __ldg(BdW + kt*512);
            uint b0, b1;
            cvt8(wv.x, b0, b1); MMA4(dacc[0], a0.x, a0.y, a0.z, a0.w, b0, b1);
            cvt8(wv.y, b0, b1); MMA4(dacc[1], a0.x, a0.y, a0.z, a0.w, b0, b1);
            cvt8(wv.z, b0, b1); MMA4(dacc[2], a0.x, a0.y, a0.z, a0.w, b0, b1);
            cvt8(wv.w, b0, b1); MMA4(dacc[3], a0.x, a0.y, a0.z, a0.w, b0, b1);
        }
        {
            #pragma unroll
            for (int g = 0; g < 4; g++) {
                float2 b2 = *(const float2*)&db[g*128 + e0d];
                dacc[g][0] = dacc[g][0]*WISCALE + b2.x;
                dacc[g][1] = dacc[g][1]*WISCALE + b2.y;
                dacc[g][2] = dacc[g][2]*WISCALE + b2.x;
                dacc[g][3] = dacc[g][3]*WISCALE + b2.y;
            }
            float hdv[4];
            #pragma unroll
            for (int c = 0; c < 4; c++) {
                bool v = (c < 2) ? v0 : v1;
                float c2 = sigm(dacc[1][c])*cd[c] + sigm(dacc[0][c])*tanhap(dacc[2][c]);
                float hh = sigm(dacc[3][c])*tanhap(c2);
                if (!v) { c2 = 0.f; hh = 0.f; }
                cd[c] = c2;
                hdv[c] = hh;
            }
            *(float2*)&hdc[r0*128 + e0d] = make_float2(hdv[0], hdv[1]);
            *(float2*)&hdc[r1*128 + e0d] = make_float2(hdv[2], hdv[3]);
            uint p01 = packh2(hdv[0], hdv[1]);
            uint p23 = packh2(hdv[2], hdv[3]);
            store_frag2(adU, r0, 128 + e0d, p01);
            store_frag2(adU, r1, 128 + e0d, p23);
            if (r0 >= 1)  store_frag2(adU, r0 - 1, 256 + e0d, p01);
            store_frag2(adU, r1 - 1, 256 + e0d, p23);
            store_frag2(adU, r0 + 1, 384 + e0d, p01);
            if (r1 <= 14) store_frag2(adU, r1 + 1, 384 + e0d, p23);
            if (r0 == 1)  { float* P = g_pub[t&1][bb][tile][0]; P[128 + e0d] = hdv[0]; P[128 + e0d + 1] = hdv[1]; }
            if (r1 == 14) { float* P = g_pub[t&1][bb][tile][1]; P[128 + e0d] = hdv[2]; P[128 + e0d + 1] = hdv[3]; }
            // next-step ns A fragments from hv
            uint q01 = packh2(hv[0], hv[1]);
            uint q23 = packh2(hv[2], hv[3]);
            uint* F = set ? AsU : AnU;
            store_frag2(F, r0, e0, q01);
            store_frag2(F, r1, e0, q23);
            if (r0 >= 1)  store_frag2(F, r0 - 1, 64 + e0, q01);
            store_frag2(F, r1 - 1, 64 + e0, q23);
            store_frag2(F, r0 + 1, 128 + e0, q01);
            if (r1 <= 14) store_frag2(F, r1 + 1, 128 + e0, q23);
        }
        __syncthreads();

        // flag release (all pubs of step t complete)
        if (tid == 0) {
            __threadfence();
            *(volatile int*)&g_flag[bb*NTILE + tile] = t + 1;
        }

        // ---- heads + output write, per-warp, post-flag (no extra sync) ----
        if (t >= 20 && w >= 1) {
            int rr = w;                 // site row 1..15
            int sg = s0 + rr - 1;
            if (sg < S) {
                float a0 = 0.f, a1 = 0.f, a2 = 0.f;
                #pragma unroll
                for (int kk = lane; kk < DH; kk += 32) {
                    float x = hdc[rr*DH + kk];
                    float y = hdc[(rr-1)*DH + kk];
                    float wn = __ldg(&onW[kk]);
                    float ws = __ldg(&osW[kk]);
                    a0 += x*wn; a1 += y*wn; a2 += x*ws;
                }
                #pragma unroll
                for (int d = 16; d >= 1; d >>= 1) {
                    a0 += __shfl_xor_sync(0xffffffffu, a0, d);
                    a1 += __shfl_xor_sync(0xffffffffu, a1, d);
                    a2 += __shfl_xor_sync(0xffffffffu, a2, d);
                }
                if (lane == 0) {
                    float onb0 = onb[0], osb0 = osb[0];
                    float o0  = a0 + onb0;
                    float o0m = a1 + onb0;
                    float o1  = a2 + osb0;
                    float inflow, spd;
                    if (sg == 0) {
                        inflow = xg[(((size_t)bb*T + (t+1))*S + 0)*4 + 1];
                        spd    = xg[(((size_t)bb*T + (t+1))*S + 0)*4 + 3];
                    } else {
                        inflow = o0m;
                        spd    = o1;
                    }
                    float numc = xin[rr*4 + 2] + inflow - o0;
                    float* o = out + ((((size_t)bb*TOUT) + (t - 20))*S + sg)*4;
                    o[0] = o0; o[1] = inflow; o[2] = numc; o[3] = spd;
                }
            }
        }
        // no sync: next Phase A touches only Ad kt8-15 (written before Phase D sync);
        // xin/hdc reads above complete before the Phase-A-end sync of step t+1.
    }
}

extern "C" void kernel_launch(void* const* d_in, const int* in_sizes, int n_in,
                              void* d_out, int out_size) {
    const float* xg  = (const float*)d_in[0];
    const float* nWx = (const float*)d_in[1];
    const float* nWh = (const float*)d_in[2];
    const float* nWa = (const float*)d_in[3];
    const float* nWb = (const float*)d_in[4];
    const float* nb  = (const float*)d_in[5];
    const float* sWx = (const float*)d_in[6];
    const float* sWh = (const float*)d_in[7];
    const float* sWa = (const float*)d_in[8];
    const float* sWb = (const float*)d_in[9];
    const float* sb  = (const float*)d_in[10];
    const float* dWx = (const float*)d_in[11];
    const float* dWh = (const float*)d_in[12];
    const float* dWa = (const float*)d_in[13];
    const float* dWb = (const float*)d_in[14];
    const float* db  = (const float*)d_in[15];
    const float* onW = (const float*)d_in[16];
    const float* onb = (const float*)d_in[17];
    const float* osW = (const float*)d_in[18];
    const float* osb = (const float*)d_in[19];
    float* out = (float*)d_out;

    (void)in_sizes; (void)n_in; (void)out_size;

    const int smem_bytes = SMEM_FLOATS * (int)sizeof(float);
    cudaFuncSetAttribute(persistent_kernel,
                         cudaFuncAttributeMaxDynamicSharedMemorySize, smem_bytes);

    init_flags_kernel<<<1, 256>>>();
    int repack_threads = 32*16*32 + 2*12*8*32;
    repack_kernel<<<(repack_threads + 255) / 256, 256>>>(
        nWh, nWa, nWb, sWh, sWa, sWb, dWx, dWh, dWa, dWb);

    dim3 grid(NTILE, NB);
    persistent_kernel<<<grid, TPB, smem_bytes>>>(
        xg, nWx, nb, sWx, sb, db, onW, onb, osW, osb, out);
}